// round 2
// baseline (speedup 1.0000x reference)
#include <cuda_runtime.h>
#include <math.h>

#define B_   32
#define N_   51
#define F_   4
#define P_   137
#define E_   408
#define NE_  (E_ + N_)      // 459 edges incl self-loops
#define EMB_ 32
#define ROW_ (N_ * EMB_)    // 1632
#define BN_  (B_ * ROW_)    // 52224

// Static device scratch (no allocations allowed)
__device__ float g_scratch[(size_t)P_ * B_ * ROW_];   // 28.6 MB: Hp*prob per (p,b,n,e)
__device__ float g_h[B_ * ROW_];                      // attention-reduced, relu'd
__device__ int   g_srcs[NE_];
__device__ float g_norms[NE_];
__device__ int   g_rp[N_ + 1];
__device__ float g_probs[P_];

// ---------------------------------------------------------------------------
// Setup: deterministic CSR-by-dst with symmetric GCN norm + softmax(attention)
// ---------------------------------------------------------------------------
__global__ void setup_kernel(const int* __restrict__ edge_index,
                             const float* __restrict__ attention) {
    __shared__ int   s_src[E_];
    __shared__ int   s_dst[E_];
    __shared__ float s_dinv[N_];
    __shared__ int   s_cnt[N_];
    __shared__ int   s_rp[N_ + 1];
    int tid = threadIdx.x;

    for (int i = tid; i < E_; i += blockDim.x) {
        s_src[i] = edge_index[i];
        s_dst[i] = edge_index[E_ + i];
    }
    __syncthreads();

    if (tid < N_) {
        int c = 1;  // self loop
        for (int e = 0; e < E_; e++) c += (s_dst[e] == tid) ? 1 : 0;
        s_cnt[tid]  = c;
        s_dinv[tid] = rsqrtf((float)c);
    }
    __syncthreads();

    if (tid == 0) {
        int acc = 0;
        for (int n = 0; n < N_; n++) { s_rp[n] = acc; acc += s_cnt[n]; }
        s_rp[N_] = acc;
        for (int n = 0; n <= N_; n++) g_rp[n] = s_rp[n];
    }
    __syncthreads();

    if (tid < N_) {
        int   k  = s_rp[tid];
        float dn = s_dinv[tid];
        for (int e = 0; e < E_; e++) {
            if (s_dst[e] == tid) {
                int s = s_src[e];
                g_srcs[k]  = s;
                g_norms[k] = s_dinv[s] * dn;
                k++;
            }
        }
        g_srcs[k]  = tid;          // self loop last (order irrelevant to the sum)
        g_norms[k] = dn * dn;
    } else if (tid == N_) {
        float m = -1e30f;
        for (int p = 0; p < P_; p++) m = fmaxf(m, attention[p]);
        float s = 0.f;
        for (int p = 0; p < P_; p++) s += expf(attention[p] - m);
        float inv = 1.f / s;
        for (int p = 0; p < P_; p++) g_probs[p] = expf(attention[p] - m) * inv;
    }
}

// ---------------------------------------------------------------------------
// Main fused kernel: one block per (b, p).
//  stage 1: xw = x @ Wz / Wh          (smem xs, per-lane W cols)
//  stage 2: agg over CSR (+ conv bias)  -> registers (lane = channel e)
//  stage 3: gate matmuls via warp shuffle, activations, * prob, -> scratch
// ---------------------------------------------------------------------------
__global__ __launch_bounds__(256, 1) void main_kernel(
    const float* __restrict__ x,
    const float* __restrict__ Wz,  const float* __restrict__ bz,
    const float* __restrict__ Wh,  const float* __restrict__ bh,
    const float* __restrict__ lzw, const float* __restrict__ lzb,
    const float* __restrict__ lhw, const float* __restrict__ lhb)
{
    __shared__ float xs[N_ * F_];
    __shared__ float xwz[ROW_];
    __shared__ float xwh[ROW_];
    __shared__ int   s_srcS[NE_];
    __shared__ float s_nrmS[NE_];
    __shared__ int   s_rpS[N_ + 1];

    const int tid  = threadIdx.x;
    const int lane = tid & 31;
    const int w    = tid >> 5;           // 8 warps
    const int bp   = blockIdx.x;
    const int p    = bp % P_;
    const int b    = bp / P_;

    // Per-lane register weights (lane = output channel e). Global loads are
    // coalesced 128B rows, hot in L1 — no smem crossbar pressure.
    float wz1[F_], wh1[F_];
#pragma unroll
    for (int f = 0; f < F_; f++) {
        wz1[f] = Wz[f * EMB_ + lane];
        wh1[f] = Wh[f * EMB_ + lane];
    }
    float wzc[EMB_], whc[EMB_];
#pragma unroll
    for (int k = 0; k < EMB_; k++) {
        wzc[k] = lzw[k * EMB_ + lane];   // only first EMB rows matter (H == 0)
        whc[k] = lhw[k * EMB_ + lane];
    }
    const float bz_r  = bz[lane];
    const float bh_r  = bh[lane];
    const float lzb_r = lzb[lane];
    const float lhb_r = lhb[lane];

    // x slice for this (b,p): x[b, n, f, p]
    for (int i = tid; i < N_ * F_; i += 256) {
        int n = i >> 2, f = i & 3;
        xs[i] = x[(((size_t)b * N_ + n) * F_ + f) * P_ + p];
    }
    for (int i = tid; i < NE_; i += 256) {
        s_srcS[i] = g_srcs[i];
        s_nrmS[i] = g_norms[i];
    }
    if (tid <= N_) s_rpS[tid] = g_rp[tid];
    __syncthreads();

    // stage 1: xw[n][e] = sum_f xs[n][f] * W[f][e]
    for (int n = w; n < N_; n += 8) {
        float a = 0.f, c = 0.f;
#pragma unroll
        for (int f = 0; f < F_; f++) {
            float xv = xs[n * F_ + f];
            a += xv * wz1[f];
            c += xv * wh1[f];
        }
        xwz[n * EMB_ + lane] = a;
        xwh[n * EMB_ + lane] = c;
    }
    __syncthreads();

    const float prob = g_probs[p];
    float* outp = g_scratch + ((size_t)p * B_ + b) * ROW_;

    for (int n = w; n < N_; n += 8) {
        // stage 2: normalized aggregation + conv bias
        float a = bz_r, c = bh_r;
        const int j0 = s_rpS[n], j1 = s_rpS[n + 1];
        for (int j = j0; j < j1; j++) {
            int   s  = s_srcS[j];
            float wt = s_nrmS[j];
            a += wt * xwz[s * EMB_ + lane];
            c += wt * xwh[s * EMB_ + lane];
        }
        // stage 3: gate matmuls (warp-level: lane k holds agg[k], broadcast)
        float za0 = lzb_r, za1 = 0.f;
        float ha0 = lhb_r, ha1 = 0.f;
#pragma unroll
        for (int k = 0; k < EMB_; k += 2) {
            float a0 = __shfl_sync(0xffffffffu, a, k);
            float a1 = __shfl_sync(0xffffffffu, a, k + 1);
            float c0 = __shfl_sync(0xffffffffu, c, k);
            float c1 = __shfl_sync(0xffffffffu, c, k + 1);
            za0 += a0 * wzc[k];
            za1 += a1 * wzc[k + 1];
            ha0 += c0 * whc[k];
            ha1 += c1 * whc[k + 1];
        }
        float za = za0 + za1;
        float ha = ha0 + ha1;
        float z  = 1.f / (1.f + __expf(-za));
        float ht = tanhf(ha);
        outp[n * EMB_ + lane] = (1.f - z) * ht * prob;   // (1-Z)*Ht * softmax(att)[p]
    }
}

// ---------------------------------------------------------------------------
// Reduce over P (coalesced, stride BN_ between p-slices) + relu
// ---------------------------------------------------------------------------
__global__ void reduce_kernel() {
    int g = blockIdx.x * blockDim.x + threadIdx.x;
    if (g >= BN_) return;
    float s = 0.f;
#pragma unroll 4
    for (int p = 0; p < P_; p++)
        s += g_scratch[(size_t)p * BN_ + g];
    g_h[g] = fmaxf(s, 0.f);
}

// ---------------------------------------------------------------------------
// MLP head: relu(h@W1+b1) @ W2 + b2 -> per-node scalar; sigmoid(@W3 + b3) per b
// One block per batch element.
// ---------------------------------------------------------------------------
__global__ __launch_bounds__(512) void final_kernel(
    const float* __restrict__ lin1_w, const float* __restrict__ lin1_b,
    const float* __restrict__ lin2_w, const float* __restrict__ lin2_b,
    const float* __restrict__ lin3_w, const float* __restrict__ lin3_b,
    float* __restrict__ out)
{
    __shared__ float sh[ROW_];
    __shared__ float w1[EMB_ * 32];
    __shared__ float ssum[N_];
    const int b   = blockIdx.x;
    const int tid = threadIdx.x;

    for (int i = tid; i < ROW_; i += 512) sh[i] = g_h[b * ROW_ + i];
    for (int i = tid; i < EMB_ * 32; i += 512) w1[i] = lin1_w[i];
    __syncthreads();

    for (int idx = tid; idx < N_ * 32; idx += 512) {
        int n = idx >> 5, j = idx & 31;   // j == lane (stride 512 is a multiple of 32)
        float a = lin1_b[j];
#pragma unroll
        for (int e = 0; e < EMB_; e++)
            a += sh[n * EMB_ + e] * w1[e * 32 + j];
        a = fmaxf(a, 0.f) * lin2_w[j];
#pragma unroll
        for (int o = 16; o > 0; o >>= 1)
            a += __shfl_xor_sync(0xffffffffu, a, o);
        if (j == 0) ssum[n] = a;
    }
    __syncthreads();

    if (tid == 0) {
        float acc = lin3_b[0];
        float b2  = lin2_b[0];
        for (int n = 0; n < N_; n++)
            acc += (ssum[n] + b2) * lin3_w[n];
        out[b] = 1.f / (1.f + expf(-acc));
    }
}

// ---------------------------------------------------------------------------
extern "C" void kernel_launch(void* const* d_in, const int* in_sizes, int n_in,
                              void* d_out, int out_size) {
    const float* x   = (const float*)d_in[0];
    const int*   ei  = (const int*)  d_in[1];
    const float* czw = (const float*)d_in[2];
    const float* czb = (const float*)d_in[3];
    // d_in[4], d_in[5]: conv_r_* — R gate multiplies H == 0, DCE'd
    const float* chw = (const float*)d_in[6];
    const float* chb = (const float*)d_in[7];
    const float* lzw = (const float*)d_in[8];
    const float* lzb = (const float*)d_in[9];
    // d_in[10], d_in[11]: lin_r_* — unused
    const float* lhw = (const float*)d_in[12];
    const float* lhb = (const float*)d_in[13];
    const float* att = (const float*)d_in[14];
    const float* l1w = (const float*)d_in[15];
    const float* l1b = (const float*)d_in[16];
    const float* l2w = (const float*)d_in[17];
    const float* l2b = (const float*)d_in[18];
    const float* l3w = (const float*)d_in[19];
    const float* l3b = (const float*)d_in[20];
    float* out = (float*)d_out;

    setup_kernel<<<1, 128>>>(ei, att);
    main_kernel<<<B_ * P_, 256>>>(x, czw, czb, chw, chb, lzw, lzb, lhw, lhb);
    reduce_kernel<<<(BN_ + 255) / 256, 256>>>();
    final_kernel<<<B_, 512>>>(l1w, l1b, l2w, l2b, l3w, l3b, out);
}

// round 3
// speedup vs baseline: 4.0426x; 4.0426x over previous
#include <cuda_runtime.h>
#include <math.h>

#define B_   32
#define N_   51
#define F_   4
#define P_   137
#define E_   408
#define NE_  (E_ + N_)      // 459 edges incl self-loops
#define EMB_ 32
#define NF_  (N_ * F_)      // 204
#define ROW_ (N_ * EMB_)    // 1632
#define CH_  9              // P chunks
#define PC_  16             // p per chunk (last chunk: 9)

// Static device scratch
__device__ float g_part[(size_t)CH_ * B_ * ROW_];   // 2.09 MB partial accumulators
__device__ int   g_srcs[NE_];
__device__ float g_norms[NE_];
__device__ int   g_rp[N_ + 1];
__device__ float g_probs[P_];
__device__ float g_wz[F_ * EMB_], g_wh[F_ * EMB_];  // composed conv@gate weights
__device__ float g_bz[EMB_], g_bh[EMB_];            // composed biases

// ---------------------------------------------------------------------------
// Setup: parallel deterministic CSR (ballot/popc stable order), softmax,
// and weight composition  Mz = conv_z_w @ lin_z_w[:32], bz' = bz@lzw + lzb.
// ---------------------------------------------------------------------------
__global__ __launch_bounds__(512) void setup_kernel(
    const int* __restrict__ ei, const float* __restrict__ att,
    const float* __restrict__ czw, const float* __restrict__ czb,
    const float* __restrict__ chw, const float* __restrict__ chb,
    const float* __restrict__ lzw, const float* __restrict__ lzb,
    const float* __restrict__ lhw, const float* __restrict__ lhb)
{
    __shared__ int   s_src[E_], s_dst[E_];
    __shared__ float s_dinv[N_];
    __shared__ int   s_cnt[N_], s_rp[N_ + 1];
    const int tid = threadIdx.x, lane = tid & 31, w = tid >> 5;

    for (int i = tid; i < E_; i += 512) { s_src[i] = ei[i]; s_dst[i] = ei[E_ + i]; }
    __syncthreads();

    // degrees: one warp per node, popc(ballot) is lane-uniform
    for (int n = w; n < N_; n += 16) {
        int c = 0;
        for (int base = 0; base < E_; base += 32) {
            int j = base + lane;
            bool m = (j < E_) && (s_dst[j] == n);
            c += __popc(__ballot_sync(0xffffffffu, m));
        }
        if (lane == 0) { s_cnt[n] = c + 1; s_dinv[n] = rsqrtf((float)(c + 1)); }
    }
    __syncthreads();

    if (tid == 0) {
        int a = 0;
        for (int n = 0; n < N_; n++) { s_rp[n] = a; a += s_cnt[n]; }
        s_rp[N_] = a;
        for (int n = 0; n <= N_; n++) g_rp[n] = s_rp[n];
    }
    __syncthreads();

    // CSR fill (stable edge order via ballot prefix -> deterministic)
    for (int n = w; n < N_; n += 16) {
        int wr = s_rp[n];
        float dn = s_dinv[n];
        for (int base = 0; base < E_; base += 32) {
            int j = base + lane;
            bool m = (j < E_) && (s_dst[j] == n);
            unsigned msk = __ballot_sync(0xffffffffu, m);
            if (m) {
                int pos = wr + __popc(msk & ((1u << lane) - 1u));
                int s = s_src[j];
                g_srcs[pos]  = s;
                g_norms[pos] = s_dinv[s] * dn;
            }
            wr += __popc(msk);
        }
        if (lane == 0) { g_srcs[wr] = n; g_norms[wr] = dn * dn; }  // self loop
    }

    // softmax(attention) on warp 0
    if (w == 0) {
        float mx = -1e30f;
        for (int p = lane; p < P_; p += 32) mx = fmaxf(mx, att[p]);
        #pragma unroll
        for (int o = 16; o; o >>= 1) mx = fmaxf(mx, __shfl_xor_sync(0xffffffffu, mx, o));
        float s = 0.f;
        for (int p = lane; p < P_; p += 32) s += __expf(att[p] - mx);
        #pragma unroll
        for (int o = 16; o; o >>= 1) s += __shfl_xor_sync(0xffffffffu, s, o);
        float inv = 1.f / s;
        for (int p = lane; p < P_; p += 32) g_probs[p] = __expf(att[p] - mx) * inv;
    }

    // weight composition
    if (tid >= 32 && tid < 160) {
        int t = tid - 32, f = t >> 5, e = t & 31;
        float a = 0.f;
        #pragma unroll
        for (int k = 0; k < EMB_; k++) a += czw[f * EMB_ + k] * lzw[k * EMB_ + e];
        g_wz[f * EMB_ + e] = a;
    } else if (tid >= 160 && tid < 288) {
        int t = tid - 160, f = t >> 5, e = t & 31;
        float a = 0.f;
        #pragma unroll
        for (int k = 0; k < EMB_; k++) a += chw[f * EMB_ + k] * lhw[k * EMB_ + e];
        g_wh[f * EMB_ + e] = a;
    } else if (tid >= 288 && tid < 320) {
        int e = tid - 288; float a = lzb[e];
        #pragma unroll
        for (int k = 0; k < EMB_; k++) a += czb[k] * lzw[k * EMB_ + e];
        g_bz[e] = a;
    } else if (tid >= 320 && tid < 352) {
        int e = tid - 320; float a = lhb[e];
        #pragma unroll
        for (int k = 0; k < EMB_; k++) a += chb[k] * lhw[k * EMB_ + e];
        g_bh[e] = a;
    }
}

// ---------------------------------------------------------------------------
// Main: block = (b, p-chunk).  agg_x = A @ x (4 channels), then 4->32
// composed transform + gated activation, accumulated over p in registers.
// ---------------------------------------------------------------------------
__global__ __launch_bounds__(256, 2) void main_kernel(const float* __restrict__ x)
{
    __shared__ float xt  [NF_ * (PC_ + 1)];   // [204][17] padded
    __shared__ float aggs[NF_ * (PC_ + 1)];
    __shared__ int   s_srcs[NE_];
    __shared__ float s_nrm[NE_];
    __shared__ int   s_rp[N_ + 1];
    __shared__ float s_probs[PC_];

    const int tid = threadIdx.x, lane = tid & 31, w = tid >> 5;
    const int c  = blockIdx.x % CH_;
    const int b  = blockIdx.x / CH_;
    const int p0 = c * PC_;
    const int pc = min(PC_, P_ - p0);

    // per-lane composed weights (lane = output channel e)
    float wz[F_], wh[F_];
    #pragma unroll
    for (int f = 0; f < F_; f++) { wz[f] = g_wz[f * EMB_ + lane]; wh[f] = g_wh[f * EMB_ + lane]; }
    const float bzr = g_bz[lane], bhr = g_bh[lane];

    for (int i = tid; i < NE_; i += 256) { s_srcs[i] = g_srcs[i]; s_nrm[i] = g_norms[i]; }
    if (tid <= N_) s_rp[tid] = g_rp[tid];
    if (tid < pc)  s_probs[tid] = g_probs[p0 + tid];

    // load x rows: x[b, nf, p0:p0+pc] (contiguous along p)
    const float* xb = x + (size_t)b * NF_ * P_ + p0;
    for (int r = w; r < NF_; r += 8)
        if (lane < pc) xt[r * (PC_ + 1) + lane] = xb[r * P_ + lane];
    __syncthreads();

    // aggregate A @ x for all (nf, p) in chunk
    for (int i = tid; i < NF_ * PC_; i += 256) {
        int nf = i >> 4, p = i & 15;
        if (p < pc) {
            int n = nf >> 2, f = nf & 3;
            float a = 0.f;
            const int j1 = s_rp[n + 1];
            for (int j = s_rp[n]; j < j1; j++)
                a += s_nrm[j] * xt[(s_srcs[j] * F_ + f) * (PC_ + 1) + p];
            aggs[nf * (PC_ + 1) + p] = a;
        }
    }
    __syncthreads();

    // transform + activations, accumulate over p in registers
    float acc[7];
    #pragma unroll
    for (int k = 0; k < 7; k++) acc[k] = 0.f;

    for (int p = 0; p < pc; p++) {
        const float pr = s_probs[p];
        #pragma unroll
        for (int k = 0; k < 7; k++) {
            int n = w + 8 * k;             // item i = tid + 256k  <->  n = w+8k, e = lane
            if (n >= N_) break;
            const float* ag = &aggs[(n * F_) * (PC_ + 1) + p];
            float a0 = ag[0], a1 = ag[PC_ + 1], a2 = ag[2 * (PC_ + 1)], a3 = ag[3 * (PC_ + 1)];
            float za  = bzr + a0 * wz[0] + a1 * wz[1] + a2 * wz[2] + a3 * wz[3];
            float ha2 = 2.f * (bhr + a0 * wh[0] + a1 * wh[1] + a2 * wh[2] + a3 * wh[3]);
            za  = fminf(fmaxf(za,  -20.f), 20.f);
            ha2 = fminf(fmaxf(ha2, -40.f), 40.f);
            float u = __expf(za);          // e^za
            float v = __expf(ha2);         // e^{2ha}
            // (1 - sigmoid(za)) * tanh(ha) = (v-1) / ((1+u)(1+v))
            float val = __fdividef(v - 1.f, (1.f + u) * (1.f + v));
            acc[k] += pr * val;
        }
    }

    float* op = g_part + (size_t)(c * B_ + b) * ROW_;
    #pragma unroll
    for (int k = 0; k < 7; k++) {
        int i = tid + 256 * k;
        if (i < ROW_) op[i] = acc[k];
    }
}

// ---------------------------------------------------------------------------
// Final: fold chunk-reduction + relu + MLP head + per-b sigmoid.
// ---------------------------------------------------------------------------
__global__ __launch_bounds__(512) void final_kernel(
    const float* __restrict__ l1w, const float* __restrict__ l1b,
    const float* __restrict__ l2w, const float* __restrict__ l2b,
    const float* __restrict__ l3w, const float* __restrict__ l3b,
    float* __restrict__ out)
{
    __shared__ float sh[ROW_];
    __shared__ float w1[EMB_ * 32];
    __shared__ float ssum[N_ + 1];
    const int b = blockIdx.x, tid = threadIdx.x, lane = tid & 31;

    for (int i = tid; i < ROW_; i += 512) {
        float s = 0.f;
        #pragma unroll
        for (int cc = 0; cc < CH_; cc++)
            s += g_part[(size_t)(cc * B_ + b) * ROW_ + i];
        sh[i] = fmaxf(s, 0.f);
    }
    for (int i = tid; i < EMB_ * 32; i += 512) w1[i] = l1w[i];
    __syncthreads();

    const float w2j = l2w[lane];
    const float b1j = l1b[lane];
    for (int idx = tid; idx < N_ * 32; idx += 512) {
        int n = idx >> 5;                  // j == lane (512 is a multiple of 32)
        float a = b1j;
        #pragma unroll
        for (int e = 0; e < EMB_; e++) a += sh[n * EMB_ + e] * w1[e * 32 + lane];
        a = fmaxf(a, 0.f) * w2j;
        #pragma unroll
        for (int o = 16; o; o >>= 1) a += __shfl_xor_sync(0xffffffffu, a, o);
        if (lane == 0) ssum[n] = a;
    }
    __syncthreads();

    if (tid < 32) {
        float v = 0.f;
        const float b2 = l2b[0];
        for (int n = lane; n < N_; n += 32) v += (ssum[n] + b2) * l3w[n];
        #pragma unroll
        for (int o = 16; o; o >>= 1) v += __shfl_xor_sync(0xffffffffu, v, o);
        if (lane == 0) out[b] = 1.f / (1.f + __expf(-(v + l3b[0])));
    }
}

// ---------------------------------------------------------------------------
extern "C" void kernel_launch(void* const* d_in, const int* in_sizes, int n_in,
                              void* d_out, int out_size) {
    const float* x   = (const float*)d_in[0];
    const int*   ei  = (const int*)  d_in[1];
    const float* czw = (const float*)d_in[2];
    const float* czb = (const float*)d_in[3];
    // d_in[4..5]: conv_r_* unused (R gate multiplies H == 0)
    const float* chw = (const float*)d_in[6];
    const float* chb = (const float*)d_in[7];
    const float* lzw = (const float*)d_in[8];
    const float* lzb = (const float*)d_in[9];
    // d_in[10..11]: lin_r_* unused
    const float* lhw = (const float*)d_in[12];
    const float* lhb = (const float*)d_in[13];
    const float* att = (const float*)d_in[14];
    const float* l1w = (const float*)d_in[15];
    const float* l1b = (const float*)d_in[16];
    const float* l2w = (const float*)d_in[17];
    const float* l2b = (const float*)d_in[18];
    const float* l3w = (const float*)d_in[19];
    const float* l3b = (const float*)d_in[20];
    float* out = (float*)d_out;

    setup_kernel<<<1, 512>>>(ei, att, czw, czb, chw, chb, lzw, lzb, lhw, lhb);
    main_kernel<<<B_ * CH_, 256>>>(x);
    final_kernel<<<B_, 512>>>(l1w, l1b, l2w, l2b, l3w, l3b, out);
}

// round 4
// speedup vs baseline: 4.8718x; 1.2051x over previous
#include <cuda_runtime.h>
#include <math.h>

#define B_   32
#define N_   51
#define F_   4
#define P_   137
#define E_   408
#define NE_  (E_ + N_)      // 459 edges incl self-loops
#define EMB_ 32
#define NF_  (N_ * F_)      // 204
#define ROW_ (N_ * EMB_)    // 1632
#define CH_  9              // P chunks
#define PC_  16             // p per chunk (last chunk: 9)
#define LOG2E 1.4426950408889634f

// Static device scratch
__device__ float g_part[(size_t)CH_ * B_ * ROW_];   // 2.09 MB partial accumulators
__device__ int   g_srcs[NE_];
__device__ float g_norms[NE_];
__device__ int   g_rp[N_ + 1];
__device__ float g_probs[P_];
__device__ float g_wz[F_ * EMB_], g_wh[F_ * EMB_];  // composed, pre-scaled by log2e
__device__ float g_bz[EMB_], g_bh[EMB_];

__device__ __forceinline__ float ex2(float x) {
    float r;
    asm("ex2.approx.ftz.f32 %0, %1;" : "=f"(r) : "f"(x));
    return r;
}

// ---------------------------------------------------------------------------
// Setup: fully parallel, deterministic.
//  Phase A (pre-barrier, disjoint thread ranges): edge load | weight
//  composition | softmax.  Phase B: int-atomic degrees (deterministic).
//  Phase C: warp-shuffle prefix scan.  Phase D: per-edge rank (stable) + fill.
// ---------------------------------------------------------------------------
__global__ __launch_bounds__(512) void setup_kernel(
    const int* __restrict__ ei, const float* __restrict__ att,
    const float* __restrict__ czw, const float* __restrict__ czb,
    const float* __restrict__ chw, const float* __restrict__ chb,
    const float* __restrict__ lzw, const float* __restrict__ lzb,
    const float* __restrict__ lhw, const float* __restrict__ lhb)
{
    __shared__ int   s_src[E_], s_dst[E_];
    __shared__ float s_dinv[N_];
    __shared__ int   s_deg[N_];
    __shared__ int   s_rp[N_ + 1];
    const int tid = threadIdx.x, lane = tid & 31;

    // --- Phase A: disjoint work before first barrier ---
    if (tid < 128) {
        if (tid < N_) s_deg[tid] = 0;
        for (int i = tid; i < E_; i += 128) { s_src[i] = ei[i]; s_dst[i] = ei[E_ + i]; }
    } else if (tid < 256) {
        int t = tid - 128, f = t >> 5, e = t & 31;      // g_wz: 4x32
        float a = 0.f;
        #pragma unroll
        for (int k = 0; k < EMB_; k++) a += czw[f * EMB_ + k] * lzw[k * EMB_ + e];
        g_wz[f * EMB_ + e] = a * LOG2E;
    } else if (tid < 384) {
        int t = tid - 256, f = t >> 5, e = t & 31;      // g_wh: 4x32 (x2 for tanh)
        float a = 0.f;
        #pragma unroll
        for (int k = 0; k < EMB_; k++) a += chw[f * EMB_ + k] * lhw[k * EMB_ + e];
        g_wh[f * EMB_ + e] = a * (2.f * LOG2E);
    } else if (tid < 416) {
        int e = tid - 384; float a = lzb[e];
        #pragma unroll
        for (int k = 0; k < EMB_; k++) a += czb[k] * lzw[k * EMB_ + e];
        g_bz[e] = a * LOG2E;
    } else if (tid < 448) {
        int e = tid - 416; float a = lhb[e];
        #pragma unroll
        for (int k = 0; k < EMB_; k++) a += chb[k] * lhw[k * EMB_ + e];
        g_bh[e] = a * (2.f * LOG2E);
    } else if (tid < 480) {
        // softmax(attention), warp 14
        float mx = -1e30f;
        for (int p = lane; p < P_; p += 32) mx = fmaxf(mx, att[p]);
        #pragma unroll
        for (int o = 16; o; o >>= 1) mx = fmaxf(mx, __shfl_xor_sync(0xffffffffu, mx, o));
        float s = 0.f;
        for (int p = lane; p < P_; p += 32) s += __expf(att[p] - mx);
        #pragma unroll
        for (int o = 16; o; o >>= 1) s += __shfl_xor_sync(0xffffffffu, s, o);
        float inv = 1.f / s;
        for (int p = lane; p < P_; p += 32) g_probs[p] = __expf(att[p] - mx) * inv;
    }
    __syncthreads();

    // --- Phase B: degrees via integer atomics (associative -> deterministic) ---
    if (tid < 128)
        for (int e = tid; e < E_; e += 128) atomicAdd(&s_deg[s_dst[e]], 1);
    __syncthreads();

    if (tid < N_) s_dinv[tid] = rsqrtf((float)(s_deg[tid] + 1));
    __syncthreads();

    // --- Phase C: prefix scan over (deg+1), warp 0 only (51 values) ---
    if (tid < 32) {
        int v = (lane < N_) ? s_deg[lane] + 1 : 0;
        #pragma unroll
        for (int o = 1; o < 32; o <<= 1) {
            int t = __shfl_up_sync(0xffffffffu, v, o);
            if (lane >= o) v += t;
        }
        int base = __shfl_sync(0xffffffffu, v, 31);
        int v2 = (lane < N_ - 32) ? s_deg[32 + lane] + 1 : 0;
        #pragma unroll
        for (int o = 1; o < 32; o <<= 1) {
            int t = __shfl_up_sync(0xffffffffu, v2, o);
            if (lane >= o) v2 += t;
        }
        if (lane == 0) s_rp[0] = 0;
        s_rp[lane + 1] = v;
        if (lane < N_ - 32) s_rp[33 + lane] = base + v2;
    }
    __syncthreads();

    // --- Phase D: stable rank per edge + CSR fill + self loops ---
    if (tid < E_) {
        int d = s_dst[tid], s = s_src[tid];
        int r = 0;
        for (int e2 = 0; e2 < tid; e2++) r += (s_dst[e2] == d) ? 1 : 0;
        int pos = s_rp[d] + r;
        g_srcs[pos]  = s;
        g_norms[pos] = s_dinv[s] * s_dinv[d];
    } else if (tid < NE_) {
        int n = tid - E_;
        int pos = s_rp[n + 1] - 1;       // self loop in last slot
        float dn = s_dinv[n];
        g_srcs[pos]  = n;
        g_norms[pos] = dn * dn;
    }
    if (tid <= N_) g_rp[tid] = s_rp[tid];
}

// ---------------------------------------------------------------------------
// Main: block = (b, p-chunk).  agg = A @ x (4 channels), then composed 4->32
// transform + gated activation in exp2 domain, accumulated over p in regs.
// ---------------------------------------------------------------------------
__global__ __launch_bounds__(256, 2) void main_kernel(const float* __restrict__ x)
{
    __shared__ float xt  [NF_ * (PC_ + 1)];
    __shared__ float aggs[NF_ * (PC_ + 1)];
    __shared__ int   s_srcs[NE_];
    __shared__ float s_nrm[NE_];
    __shared__ int   s_rp[N_ + 1];
    __shared__ float s_probs[PC_];

    const int tid = threadIdx.x, lane = tid & 31, w = tid >> 5;
    const int c  = blockIdx.x % CH_;
    const int b  = blockIdx.x / CH_;
    const int p0 = c * PC_;
    const int pc = min(PC_, P_ - p0);

    float wz[F_], wh[F_];
    #pragma unroll
    for (int f = 0; f < F_; f++) { wz[f] = g_wz[f * EMB_ + lane]; wh[f] = g_wh[f * EMB_ + lane]; }
    const float bzr = g_bz[lane], bhr = g_bh[lane];

    for (int i = tid; i < NE_; i += 256) { s_srcs[i] = g_srcs[i]; s_nrm[i] = g_norms[i]; }
    if (tid <= N_) s_rp[tid] = g_rp[tid];
    if (tid < pc)  s_probs[tid] = g_probs[p0 + tid];

    const float* xb = x + (size_t)b * NF_ * P_ + p0;
    for (int r = w; r < NF_; r += 8)
        if (lane < pc) xt[r * (PC_ + 1) + lane] = xb[r * P_ + lane];
    __syncthreads();

    for (int i = tid; i < NF_ * PC_; i += 256) {
        int nf = i >> 4, p = i & 15;
        if (p < pc) {
            int n = nf >> 2, f = nf & 3;
            float a = 0.f;
            const int j1 = s_rp[n + 1];
            for (int j = s_rp[n]; j < j1; j++)
                a += s_nrm[j] * xt[(s_srcs[j] * F_ + f) * (PC_ + 1) + p];
            aggs[nf * (PC_ + 1) + p] = a;
        }
    }
    __syncthreads();

    float acc[7];
    #pragma unroll
    for (int k = 0; k < 7; k++) acc[k] = 0.f;

    for (int p = 0; p < pc; p++) {
        const float pr = s_probs[p];
        #pragma unroll
        for (int k = 0; k < 7; k++) {
            int n = w + 8 * k;
            if (n >= N_) break;
            const float* ag = &aggs[(n * F_) * (PC_ + 1) + p];
            float a0 = ag[0], a1 = ag[PC_ + 1], a2 = ag[2 * (PC_ + 1)], a3 = ag[3 * (PC_ + 1)];
            // za2 = za*log2e ; hb2 = 2*ha*log2e  (scales folded into weights)
            float za2 = bzr + a0 * wz[0] + a1 * wz[1] + a2 * wz[2] + a3 * wz[3];
            float hb2 = bhr + a0 * wh[0] + a1 * wh[1] + a2 * wh[2] + a3 * wh[3];
            za2 = fminf(fmaxf(za2, -60.f), 60.f);
            hb2 = fminf(fmaxf(hb2, -60.f), 60.f);
            float u = ex2(za2);            // e^za
            float v = ex2(hb2);            // e^{2ha}
            // (1 - sigmoid(za)) * tanh(ha) = (v-1) / ((1+u)(1+v))
            float val = __fdividef(v - 1.f, (1.f + u) * (1.f + v));
            acc[k] += pr * val;
        }
    }

    float* op = g_part + (size_t)(c * B_ + b) * ROW_;
    #pragma unroll
    for (int k = 0; k < 7; k++) {
        int i = tid + 256 * k;
        if (i < ROW_) op[i] = acc[k];
    }
}

// ---------------------------------------------------------------------------
// Final: float4 chunk-reduction + relu + MLP head + per-b sigmoid.
// ---------------------------------------------------------------------------
__global__ __launch_bounds__(512) void final_kernel(
    const float* __restrict__ l1w, const float* __restrict__ l1b,
    const float* __restrict__ l2w, const float* __restrict__ l2b,
    const float* __restrict__ l3w, const float* __restrict__ l3b,
    float* __restrict__ out)
{
    __shared__ float sh[ROW_];
    __shared__ float w1[EMB_ * 32];
    __shared__ float ssum[N_ + 1];
    const int b = blockIdx.x, tid = threadIdx.x, lane = tid & 31;

    // chunk reduction with float4 (ROW_ = 408 float4)
    if (tid < ROW_ / 4) {
        const float4* gp = (const float4*)(g_part + (size_t)b * ROW_) + tid;
        const size_t stride4 = (size_t)B_ * ROW_ / 4;
        float4 s = make_float4(0.f, 0.f, 0.f, 0.f);
        #pragma unroll
        for (int cc = 0; cc < CH_; cc++) {
            float4 v = gp[cc * stride4];
            s.x += v.x; s.y += v.y; s.z += v.z; s.w += v.w;
        }
        float4* shp = (float4*)sh;
        shp[tid] = make_float4(fmaxf(s.x, 0.f), fmaxf(s.y, 0.f),
                               fmaxf(s.z, 0.f), fmaxf(s.w, 0.f));
    }
    for (int i = tid; i < EMB_ * 32; i += 512) w1[i] = l1w[i];
    __syncthreads();

    const float w2j = l2w[lane];
    const float b1j = l1b[lane];
    for (int idx = tid; idx < N_ * 32; idx += 512) {
        int n = idx >> 5;
        float a = b1j;
        #pragma unroll
        for (int e = 0; e < EMB_; e++) a += sh[n * EMB_ + e] * w1[e * 32 + lane];
        a = fmaxf(a, 0.f) * w2j;
        #pragma unroll
        for (int o = 16; o; o >>= 1) a += __shfl_xor_sync(0xffffffffu, a, o);
        if (lane == 0) ssum[n] = a;
    }
    __syncthreads();

    if (tid < 32) {
        float v = 0.f;
        const float b2 = l2b[0];
        for (int n = lane; n < N_; n += 32) v += (ssum[n] + b2) * l3w[n];
        #pragma unroll
        for (int o = 16; o; o >>= 1) v += __shfl_xor_sync(0xffffffffu, v, o);
        if (lane == 0) out[b] = 1.f / (1.f + __expf(-(v + l3b[0])));
    }
}

// ---------------------------------------------------------------------------
extern "C" void kernel_launch(void* const* d_in, const int* in_sizes, int n_in,
                              void* d_out, int out_size) {
    const float* x   = (const float*)d_in[0];
    const int*   ei  = (const int*)  d_in[1];
    const float* czw = (const float*)d_in[2];
    const float* czb = (const float*)d_in[3];
    // d_in[4..5]: conv_r_* unused (R gate multiplies H == 0)
    const float* chw = (const float*)d_in[6];
    const float* chb = (const float*)d_in[7];
    const float* lzw = (const float*)d_in[8];
    const float* lzb = (const float*)d_in[9];
    // d_in[10..11]: lin_r_* unused
    const float* lhw = (const float*)d_in[12];
    const float* lhb = (const float*)d_in[13];
    const float* att = (const float*)d_in[14];
    const float* l1w = (const float*)d_in[15];
    const float* l1b = (const float*)d_in[16];
    const float* l2w = (const float*)d_in[17];
    const float* l2b = (const float*)d_in[18];
    const float* l3w = (const float*)d_in[19];
    const float* l3b = (const float*)d_in[20];
    float* out = (float*)d_out;

    setup_kernel<<<1, 512>>>(ei, att, czw, czb, chw, chb, lzw, lzb, lhw, lhb);
    main_kernel<<<B_ * CH_, 256>>>(x);
    final_kernel<<<B_, 512>>>(l1w, l1b, l2w, l2b, l3w, l3b, out);
}

// round 5
// speedup vs baseline: 5.1630x; 1.0598x over previous
#include <cuda_runtime.h>
#include <math.h>

#define B_   32
#define N_   51
#define F_   4
#define P_   137
#define E_   408
#define NE_  (E_ + N_)      // 459 edges incl self-loops
#define EMB_ 32
#define NF_  (N_ * F_)      // 204
#define ROW_ (N_ * EMB_)    // 1632
#define CH_  9              // P chunks
#define PC_  16             // p per chunk (last chunk: 9)
#define LOG2E 1.4426950408889634f

// Static device scratch
__device__ float g_part[(size_t)CH_ * B_ * ROW_];   // 2.09 MB partial accumulators

__device__ __forceinline__ float ex2(float x) {
    float r;
    asm("ex2.approx.ftz.f32 %0, %1;" : "=f"(r) : "f"(x));
    return r;
}

// ---------------------------------------------------------------------------
// Fused kernel: every block does its own (cheap, parallel) setup, then the
// per-(b, p-chunk) GNN work. Deterministic throughout.
// ---------------------------------------------------------------------------
__global__ __launch_bounds__(256, 2) void main_kernel(
    const float* __restrict__ x,   const int* __restrict__ ei,
    const float* __restrict__ czw, const float* __restrict__ czb,
    const float* __restrict__ chw, const float* __restrict__ chb,
    const float* __restrict__ lzw, const float* __restrict__ lzb,
    const float* __restrict__ lhw, const float* __restrict__ lhb,
    const float* __restrict__ att)
{
    __shared__ float xt  [NF_ * (PC_ + 1)];
    __shared__ float aggs[NF_ * (PC_ + 1)];
    __shared__ int   s_src[E_], s_dst[E_];
    __shared__ int   s_srcs[NE_];
    __shared__ float s_nrm[NE_];
    __shared__ int   s_deg[N_], s_cnt[N_];
    __shared__ float s_dinv[N_];
    __shared__ int   s_rp[N_ + 1];
    __shared__ float s_wz[F_ * EMB_], s_wh[F_ * EMB_];
    __shared__ float s_bz[EMB_], s_bh[EMB_];
    __shared__ float s_probs[PC_];

    const int tid = threadIdx.x, lane = tid & 31, w = tid >> 5;
    const int c  = blockIdx.x % CH_;
    const int b  = blockIdx.x / CH_;
    const int p0 = c * PC_;
    const int pc = min(PC_, P_ - p0);

    // ---- P0: edges, x tile, composed weights (all independent) ----
    if (tid < N_) s_deg[tid] = 0;
    for (int i = tid; i < E_; i += 256) { s_src[i] = ei[i]; s_dst[i] = ei[E_ + i]; }

    const float* xb = x + (size_t)b * NF_ * P_ + p0;
    for (int r = w; r < NF_; r += 8)
        if (lane < pc) xt[r * (PC_ + 1) + lane] = xb[r * P_ + lane];

    // weight composition: 256 threads = 256 composed elements
    if (tid < 128) {
        int f = tid >> 5, e = tid & 31;
        float a = 0.f;
        #pragma unroll
        for (int k = 0; k < EMB_; k++) a += czw[f * EMB_ + k] * lzw[k * EMB_ + e];
        s_wz[tid] = a * LOG2E;
        if (f == 0) {
            float bb = lzb[e];
            #pragma unroll
            for (int k = 0; k < EMB_; k++) bb += czb[k] * lzw[k * EMB_ + e];
            s_bz[e] = bb * LOG2E;
        }
    } else {
        int t = tid - 128, f = t >> 5, e = t & 31;
        float a = 0.f;
        #pragma unroll
        for (int k = 0; k < EMB_; k++) a += chw[f * EMB_ + k] * lhw[k * EMB_ + e];
        s_wh[t] = a * (2.f * LOG2E);
        if (f == 0) {
            float bb = lhb[e];
            #pragma unroll
            for (int k = 0; k < EMB_; k++) bb += chb[k] * lhw[k * EMB_ + e];
            s_bh[e] = bb * (2.f * LOG2E);
        }
    }
    __syncthreads();

    // ---- P1: degrees (int smem atomics -> deterministic) ----
    for (int e = tid; e < E_; e += 256) atomicAdd(&s_deg[s_dst[e]], 1);
    __syncthreads();

    // ---- P2: scan (warp 0) | softmax (warp 1) | dinv | zero counters ----
    if (w == 0) {
        int v = (lane < N_) ? s_deg[lane] + 1 : 0;
        #pragma unroll
        for (int o = 1; o < 32; o <<= 1) {
            int t = __shfl_up_sync(0xffffffffu, v, o);
            if (lane >= o) v += t;
        }
        int base = __shfl_sync(0xffffffffu, v, 31);
        int v2 = (lane < N_ - 32) ? s_deg[32 + lane] + 1 : 0;
        #pragma unroll
        for (int o = 1; o < 32; o <<= 1) {
            int t = __shfl_up_sync(0xffffffffu, v2, o);
            if (lane >= o) v2 += t;
        }
        if (lane == 0) s_rp[0] = 0;
        s_rp[lane + 1] = v;
        if (lane < N_ - 32) s_rp[33 + lane] = base + v2;
    } else if (w == 1) {
        float mx = -1e30f;
        for (int p = lane; p < P_; p += 32) mx = fmaxf(mx, att[p]);
        #pragma unroll
        for (int o = 16; o; o >>= 1) mx = fmaxf(mx, __shfl_xor_sync(0xffffffffu, mx, o));
        float s = 0.f;
        for (int p = lane; p < P_; p += 32) s += __expf(att[p] - mx);
        #pragma unroll
        for (int o = 16; o; o >>= 1) s += __shfl_xor_sync(0xffffffffu, s, o);
        float inv = 1.f / s;
        if (lane < pc) s_probs[lane] = __expf(att[p0 + lane] - mx) * inv;
    } else if (tid >= 64 && tid < 64 + N_) {
        s_dinv[tid - 64] = rsqrtf((float)(s_deg[tid - 64] + 1));
    } else if (tid >= 128 && tid < 128 + N_) {
        s_cnt[tid - 128] = 0;
    }
    __syncthreads();

    // ---- P3: CSR fill, stable order via match_any tiles (warp 0) ----
    if (w == 0) {
        #pragma unroll 1
        for (int t = 0; t < (E_ + 31) / 32; t++) {
            int e = t * 32 + lane;
            bool valid = e < E_;
            int d = valid ? s_dst[e] : -1;
            unsigned grp = __match_any_sync(0xffffffffu, d);
            int within = __popc(grp & ((1u << lane) - 1u));
            int lead   = __ffs(grp) - 1;
            int base = 0, pos = 0, s = 0;
            if (valid) {
                base = s_cnt[d];
                pos  = s_rp[d] + base + within;
                s    = s_src[e];
                s_srcs[pos] = s;
                s_nrm[pos]  = s_dinv[s] * s_dinv[d];
            }
            __syncwarp();
            if (valid && lane == lead) s_cnt[d] = base + __popc(grp);
            __syncwarp();
        }
    } else if (tid >= 32 && tid < 32 + N_) {
        // self loop in the last slot of each node's segment (order-independent sum)
        int n = tid - 32;
        // s_rp written by warp 0 in P2 (barrier passed); deg known
        int pos = s_rp[n + 1] - 1;
        float dn = s_dinv[n];
        s_srcs[pos] = n;
        s_nrm[pos]  = dn * dn;
    }
    __syncthreads();

    // ---- P4: aggregation  aggs[nf][p] = sum_j norm_j * xt[src_j*F+f][p] ----
    for (int i = tid; i < NF_ * PC_; i += 256) {
        int nf = i >> 4, p = i & 15;
        if (p < pc) {
            int n = nf >> 2, f = nf & 3;
            float a = 0.f;
            const int j1 = s_rp[n + 1];
            for (int j = s_rp[n]; j < j1; j++)
                a += s_nrm[j] * xt[(s_srcs[j] * F_ + f) * (PC_ + 1) + p];
            aggs[nf * (PC_ + 1) + p] = a;
        }
    }
    __syncthreads();

    // ---- P5: composed 4->32 transform + gated activation, acc over p ----
    float wz[F_], wh[F_];
    #pragma unroll
    for (int f = 0; f < F_; f++) { wz[f] = s_wz[f * EMB_ + lane]; wh[f] = s_wh[f * EMB_ + lane]; }
    const float bzr = s_bz[lane], bhr = s_bh[lane];

    float acc[7];
    #pragma unroll
    for (int k = 0; k < 7; k++) acc[k] = 0.f;

    for (int p = 0; p < pc; p++) {
        const float pr = s_probs[p];
        #pragma unroll
        for (int k = 0; k < 7; k++) {
            int n = w + 8 * k;
            if (n >= N_) break;
            const float* ag = &aggs[(n * F_) * (PC_ + 1) + p];
            float a0 = ag[0], a1 = ag[PC_ + 1], a2 = ag[2 * (PC_ + 1)], a3 = ag[3 * (PC_ + 1)];
            float za2 = bzr + a0 * wz[0] + a1 * wz[1] + a2 * wz[2] + a3 * wz[3];
            float hb2 = bhr + a0 * wh[0] + a1 * wh[1] + a2 * wh[2] + a3 * wh[3];
            za2 = fminf(fmaxf(za2, -60.f), 60.f);
            hb2 = fminf(fmaxf(hb2, -60.f), 60.f);
            float u = ex2(za2);            // e^za
            float v = ex2(hb2);            // e^{2ha}
            // (1 - sigmoid(za)) * tanh(ha) = (v-1) / ((1+u)(1+v))
            float val = __fdividef(v - 1.f, (1.f + u) * (1.f + v));
            acc[k] += pr * val;
        }
    }

    float* op = g_part + (size_t)(c * B_ + b) * ROW_;
    #pragma unroll
    for (int k = 0; k < 7; k++) {
        int i = tid + 256 * k;
        if (i < ROW_) op[i] = acc[k];
    }
}

// ---------------------------------------------------------------------------
// Final: float4 chunk-reduction + relu + MLP head + per-b sigmoid.
// ---------------------------------------------------------------------------
__global__ __launch_bounds__(512) void final_kernel(
    const float* __restrict__ l1w, const float* __restrict__ l1b,
    const float* __restrict__ l2w, const float* __restrict__ l2b,
    const float* __restrict__ l3w, const float* __restrict__ l3b,
    float* __restrict__ out)
{
    __shared__ float sh[ROW_];
    __shared__ float w1[EMB_ * 32];
    __shared__ float ssum[N_ + 1];
    const int b = blockIdx.x, tid = threadIdx.x, lane = tid & 31;

    if (tid < ROW_ / 4) {
        const float4* gp = (const float4*)(g_part + (size_t)b * ROW_) + tid;
        const size_t stride4 = (size_t)B_ * ROW_ / 4;
        float4 s = make_float4(0.f, 0.f, 0.f, 0.f);
        #pragma unroll
        for (int cc = 0; cc < CH_; cc++) {
            float4 v = gp[cc * stride4];
            s.x += v.x; s.y += v.y; s.z += v.z; s.w += v.w;
        }
        float4* shp = (float4*)sh;
        shp[tid] = make_float4(fmaxf(s.x, 0.f), fmaxf(s.y, 0.f),
                               fmaxf(s.z, 0.f), fmaxf(s.w, 0.f));
    }
    for (int i = tid; i < EMB_ * 32; i += 512) w1[i] = l1w[i];
    __syncthreads();

    const float w2j = l2w[lane];
    const float b1j = l1b[lane];
    for (int idx = tid; idx < N_ * 32; idx += 512) {
        int n = idx >> 5;
        float a = b1j;
        #pragma unroll
        for (int e = 0; e < EMB_; e++) a += sh[n * EMB_ + e] * w1[e * 32 + lane];
        a = fmaxf(a, 0.f) * w2j;
        #pragma unroll
        for (int o = 16; o; o >>= 1) a += __shfl_xor_sync(0xffffffffu, a, o);
        if (lane == 0) ssum[n] = a;
    }
    __syncthreads();

    if (tid < 32) {
        float v = 0.f;
        const float b2 = l2b[0];
        for (int n = lane; n < N_; n += 32) v += (ssum[n] + b2) * l3w[n];
        #pragma unroll
        for (int o = 16; o; o >>= 1) v += __shfl_xor_sync(0xffffffffu, v, o);
        if (lane == 0) out[b] = 1.f / (1.f + __expf(-(v + l3b[0])));
    }
}

// ---------------------------------------------------------------------------
extern "C" void kernel_launch(void* const* d_in, const int* in_sizes, int n_in,
                              void* d_out, int out_size) {
    const float* x   = (const float*)d_in[0];
    const int*   ei  = (const int*)  d_in[1];
    const float* czw = (const float*)d_in[2];
    const float* czb = (const float*)d_in[3];
    // d_in[4..5]: conv_r_* unused (R gate multiplies H == 0)
    const float* chw = (const float*)d_in[6];
    const float* chb = (const float*)d_in[7];
    const float* lzw = (const float*)d_in[8];
    const float* lzb = (const float*)d_in[9];
    // d_in[10..11]: lin_r_* unused
    const float* lhw = (const float*)d_in[12];
    const float* lhb = (const float*)d_in[13];
    const float* att = (const float*)d_in[14];
    const float* l1w = (const float*)d_in[15];
    const float* l1b = (const float*)d_in[16];
    const float* l2w = (const float*)d_in[17];
    const float* l2b = (const float*)d_in[18];
    const float* l3w = (const float*)d_in[19];
    const float* l3b = (const float*)d_in[20];
    float* out = (float*)d_out;

    main_kernel<<<B_ * CH_, 256>>>(x, ei, czw, czb, chw, chb, lzw, lzb, lhw, lhb, att);
    final_kernel<<<B_, 512>>>(l1w, l1b, l2w, l2b, l3w, l3b, out);
}

// round 6
// speedup vs baseline: 6.0664x; 1.1750x over previous
#include <cuda_runtime.h>
#include <math.h>

#define B_   32
#define N_   51
#define F_   4
#define P_   137
#define E_   408
#define NE_  (E_ + N_)      // 459 edges incl self-loops
#define EMB_ 32
#define NF_  (N_ * F_)      // 204
#define ROW_ (N_ * EMB_)    // 1632
#define CH_  9              // P chunks
#define PC_  16             // p per chunk (last chunk: 9)

// Static device scratch
__device__ float g_part[(size_t)CH_ * B_ * ROW_];   // 2.09 MB partial accumulators
__device__ int   g_count[B_];                        // zero-init; reset each replay

__device__ __forceinline__ float htanh(float x) {
    float r;
    asm("tanh.approx.f32 %0, %1;" : "=f"(r) : "f"(x));
    return r;
}

// ---------------------------------------------------------------------------
// Single fused kernel. Block = (b, p-chunk). Per-block parallel setup, GNN
// work, then the last-arriving block per b runs the MLP head.
// ---------------------------------------------------------------------------
__global__ __launch_bounds__(256, 2) void main_kernel(
    const float* __restrict__ x,   const int* __restrict__ ei,
    const float* __restrict__ czw, const float* __restrict__ czb,
    const float* __restrict__ chw, const float* __restrict__ chb,
    const float* __restrict__ lzw, const float* __restrict__ lzb,
    const float* __restrict__ lhw, const float* __restrict__ lhb,
    const float* __restrict__ att,
    const float* __restrict__ l1w, const float* __restrict__ l1b,
    const float* __restrict__ l2w, const float* __restrict__ l2b,
    const float* __restrict__ l3w, const float* __restrict__ l3b,
    float* __restrict__ out)
{
    __shared__ float4 xt4  [N_ * (PC_ + 1)];   // [n][p] over 4 f-channels
    __shared__ float4 aggs4[N_ * (PC_ + 1)];
    __shared__ int    s_src[E_], s_dst[E_];
    __shared__ int2   s_edge[NE_];             // {src, nrm bits}
    __shared__ int    s_deg[N_], s_cnt[N_];
    __shared__ float  s_dinv[N_];
    __shared__ int    s_rp[N_ + 1];
    __shared__ float  s_wz[F_ * EMB_], s_wh[F_ * EMB_];
    __shared__ float  s_bz[EMB_], s_bh[EMB_];
    __shared__ float  s_probs[PC_];
    __shared__ float  s_ssum[N_ + 1];
    __shared__ int    s_last;

    const int tid = threadIdx.x, lane = tid & 31, w = tid >> 5;
    const int c  = blockIdx.x % CH_;
    const int b  = blockIdx.x / CH_;
    const int p0 = c * PC_;
    const int pc = min(PC_, P_ - p0);

    // ---- P0: edges, x tile, composed weights (all independent) ----
    if (tid < N_) s_deg[tid] = 0;
    for (int i = tid; i < E_; i += 256) { s_src[i] = ei[i]; s_dst[i] = ei[E_ + i]; }

    const float* xb = x + (size_t)b * NF_ * P_ + p0;
    for (int r = w; r < NF_; r += 8) {
        int n = r >> 2, f = r & 3;
        if (lane < pc)
            ((float*)&xt4[n * (PC_ + 1) + lane])[f] = xb[r * P_ + lane];
    }

    // composed weights: wz' = 0.5*(czw@lzw), wh' = chw@lhw  (scale for tanh form)
    if (tid < 128) {
        int f = tid >> 5, e = tid & 31;
        float a = 0.f;
        #pragma unroll
        for (int k = 0; k < EMB_; k++) a += czw[f * EMB_ + k] * lzw[k * EMB_ + e];
        s_wz[tid] = a * 0.5f;
        if (f == 0) {
            float bb = lzb[e];
            #pragma unroll
            for (int k = 0; k < EMB_; k++) bb += czb[k] * lzw[k * EMB_ + e];
            s_bz[e] = bb * 0.5f;
        }
    } else {
        int t = tid - 128, f = t >> 5, e = t & 31;
        float a = 0.f;
        #pragma unroll
        for (int k = 0; k < EMB_; k++) a += chw[f * EMB_ + k] * lhw[k * EMB_ + e];
        s_wh[t] = a;
        if (f == 0) {
            float bb = lhb[e];
            #pragma unroll
            for (int k = 0; k < EMB_; k++) bb += chb[k] * lhw[k * EMB_ + e];
            s_bh[e] = bb;
        }
    }
    __syncthreads();

    // ---- P1: degrees (int smem atomics -> deterministic) ----
    for (int e = tid; e < E_; e += 256) atomicAdd(&s_deg[s_dst[e]], 1);
    __syncthreads();

    // ---- P2: scan (warp 0) | softmax (warp 1) | dinv | zero counters ----
    if (w == 0) {
        int v = (lane < N_) ? s_deg[lane] + 1 : 0;
        #pragma unroll
        for (int o = 1; o < 32; o <<= 1) {
            int t = __shfl_up_sync(0xffffffffu, v, o);
            if (lane >= o) v += t;
        }
        int base = __shfl_sync(0xffffffffu, v, 31);
        int v2 = (lane < N_ - 32) ? s_deg[32 + lane] + 1 : 0;
        #pragma unroll
        for (int o = 1; o < 32; o <<= 1) {
            int t = __shfl_up_sync(0xffffffffu, v2, o);
            if (lane >= o) v2 += t;
        }
        if (lane == 0) s_rp[0] = 0;
        s_rp[lane + 1] = v;
        if (lane < N_ - 32) s_rp[33 + lane] = base + v2;
    } else if (w == 1) {
        float mx = -1e30f;
        for (int p = lane; p < P_; p += 32) mx = fmaxf(mx, att[p]);
        #pragma unroll
        for (int o = 16; o; o >>= 1) mx = fmaxf(mx, __shfl_xor_sync(0xffffffffu, mx, o));
        float s = 0.f;
        for (int p = lane; p < P_; p += 32) s += __expf(att[p] - mx);
        #pragma unroll
        for (int o = 16; o; o >>= 1) s += __shfl_xor_sync(0xffffffffu, s, o);
        float inv = 1.f / s;
        if (lane < pc) s_probs[lane] = __expf(att[p0 + lane] - mx) * inv;
    } else if (tid >= 64 && tid < 64 + N_) {
        s_dinv[tid - 64] = rsqrtf((float)(s_deg[tid - 64] + 1));
    } else if (tid >= 128 && tid < 128 + N_) {
        s_cnt[tid - 128] = 0;
    }
    __syncthreads();

    // ---- P3: CSR fill, stable order via match_any tiles (warp 0) ----
    if (w == 0) {
        #pragma unroll 1
        for (int t = 0; t < (E_ + 31) / 32; t++) {
            int e = t * 32 + lane;
            bool valid = e < E_;
            int d = valid ? s_dst[e] : -1;
            unsigned grp = __match_any_sync(0xffffffffu, d);
            int within = __popc(grp & ((1u << lane) - 1u));
            int lead   = __ffs(grp) - 1;
            int base = 0;
            if (valid) {
                base = s_cnt[d];
                int pos = s_rp[d] + base + within;
                int s   = s_src[e];
                s_edge[pos] = make_int2(s, __float_as_int(s_dinv[s] * s_dinv[d]));
            }
            __syncwarp();
            if (valid && lane == lead) s_cnt[d] = base + __popc(grp);
            __syncwarp();
        }
    } else if (tid >= 32 && tid < 32 + N_) {
        int n = tid - 32;
        int pos = s_rp[n + 1] - 1;        // self loop in last slot
        float dn = s_dinv[n];
        s_edge[pos] = make_int2(n, __float_as_int(dn * dn));
    }
    __syncthreads();

    // ---- P4: aggregation  aggs4[n][p] = sum_j nrm_j * xt4[src_j][p] ----
    for (int i = tid; i < N_ * PC_; i += 256) {
        int n = i >> 4, p = i & 15;
        if (p < pc) {
            float4 a = make_float4(0.f, 0.f, 0.f, 0.f);
            const int j1 = s_rp[n + 1];
            for (int j = s_rp[n]; j < j1; j++) {
                int2  ed = s_edge[j];
                float wt = __int_as_float(ed.y);
                float4 xv = xt4[ed.x * (PC_ + 1) + p];
                a.x += wt * xv.x; a.y += wt * xv.y;
                a.z += wt * xv.z; a.w += wt * xv.w;
            }
            aggs4[n * (PC_ + 1) + p] = a;
        }
    }
    __syncthreads();

    // ---- P5: composed 4->32 transform + gated activation, acc over p ----
    float wz[F_], wh[F_];
    #pragma unroll
    for (int f = 0; f < F_; f++) { wz[f] = s_wz[f * EMB_ + lane]; wh[f] = s_wh[f * EMB_ + lane]; }
    const float bzr = s_bz[lane], bhr = s_bh[lane];

    float acc[7];
    #pragma unroll
    for (int k = 0; k < 7; k++) acc[k] = 0.f;

    for (int p = 0; p < pc; p++) {
        const float pr = s_probs[p];
        #pragma unroll
        for (int k = 0; k < 7; k++) {
            int n = w + 8 * k;
            if (n >= N_) break;
            float4 a = aggs4[n * (PC_ + 1) + p];
            float zh = bzr + a.x * wz[0] + a.y * wz[1] + a.z * wz[2] + a.w * wz[3]; // za/2
            float ha = bhr + a.x * wh[0] + a.y * wh[1] + a.z * wh[2] + a.w * wh[3];
            float t1 = htanh(zh);
            float t2 = htanh(ha);
            // (1 - sigmoid(za)) * tanh(ha) = (0.5 - 0.5*tanh(za/2)) * tanh(ha)
            acc[k] += pr * ((0.5f - 0.5f * t1) * t2);
        }
    }

    float* op = g_part + (size_t)(c * B_ + b) * ROW_;
    #pragma unroll
    for (int k = 0; k < 7; k++) {
        int i = tid + 256 * k;
        if (i < ROW_) op[i] = acc[k];
    }

    // ---- Tail: last-arriving block for this b runs the MLP head ----
    __threadfence();
    if (tid == 0) {
        int old = atomicAdd(&g_count[b], 1);
        s_last = (old == CH_ - 1) ? 1 : 0;
    }
    __syncthreads();
    if (!s_last) return;
    __threadfence();

    float* sh = (float*)aggs4;   // 1632 floats (fits in 13.8 KB)
    float* w1 = (float*)xt4;     // 1024 floats

    for (int i = tid; i < ROW_ / 4; i += 256) {
        const float4* gp = (const float4*)(g_part + (size_t)b * ROW_) + i;
        const size_t stride4 = (size_t)B_ * ROW_ / 4;
        float4 s = make_float4(0.f, 0.f, 0.f, 0.f);
        #pragma unroll
        for (int cc = 0; cc < CH_; cc++) {
            float4 v = gp[cc * stride4];
            s.x += v.x; s.y += v.y; s.z += v.z; s.w += v.w;
        }
        ((float4*)sh)[i] = make_float4(fmaxf(s.x, 0.f), fmaxf(s.y, 0.f),
                                       fmaxf(s.z, 0.f), fmaxf(s.w, 0.f));
    }
    for (int i = tid; i < EMB_ * 32; i += 256) w1[i] = l1w[i];
    __syncthreads();

    const float w2j = l2w[lane];
    const float b1j = l1b[lane];
    for (int idx = tid; idx < N_ * 32; idx += 256) {
        int n = idx >> 5;                  // idx&31 == lane (256 multiple of 32)
        float a = b1j;
        #pragma unroll
        for (int e = 0; e < EMB_; e++) a += sh[n * EMB_ + e] * w1[e * 32 + lane];
        a = fmaxf(a, 0.f) * w2j;
        #pragma unroll
        for (int o = 16; o; o >>= 1) a += __shfl_xor_sync(0xffffffffu, a, o);
        if (lane == 0) s_ssum[n] = a;
    }
    __syncthreads();

    if (tid < 32) {
        float v = 0.f;
        const float b2 = l2b[0];
        for (int n = lane; n < N_; n += 32) v += (s_ssum[n] + b2) * l3w[n];
        #pragma unroll
        for (int o = 16; o; o >>= 1) v += __shfl_xor_sync(0xffffffffu, v, o);
        if (lane == 0) {
            out[b] = 1.f / (1.f + __expf(-(v + l3b[0])));
            g_count[b] = 0;                // reset for next graph replay
        }
    }
}

// ---------------------------------------------------------------------------
extern "C" void kernel_launch(void* const* d_in, const int* in_sizes, int n_in,
                              void* d_out, int out_size) {
    const float* x   = (const float*)d_in[0];
    const int*   ei  = (const int*)  d_in[1];
    const float* czw = (const float*)d_in[2];
    const float* czb = (const float*)d_in[3];
    // d_in[4..5]: conv_r_* unused (R gate multiplies H == 0)
    const float* chw = (const float*)d_in[6];
    const float* chb = (const float*)d_in[7];
    const float* lzw = (const float*)d_in[8];
    const float* lzb = (const float*)d_in[9];
    // d_in[10..11]: lin_r_* unused
    const float* lhw = (const float*)d_in[12];
    const float* lhb = (const float*)d_in[13];
    const float* att = (const float*)d_in[14];
    const float* l1w = (const float*)d_in[15];
    const float* l1b = (const float*)d_in[16];
    const float* l2w = (const float*)d_in[17];
    const float* l2b = (const float*)d_in[18];
    const float* l3w = (const float*)d_in[19];
    const float* l3b = (const float*)d_in[20];
    float* out = (float*)d_out;

    main_kernel<<<B_ * CH_, 256>>>(x, ei, czw, czb, chw, chb, lzw, lzb, lhw, lhb,
                                   att, l1w, l1b, l2w, l2b, l3w, l3b, out);
}